// round 10
// baseline (speedup 1.0000x reference)
#include <cuda_runtime.h>
#include <math.h>

#define N_ 128
#define H_ 256
#define B_ 16

// -------- device scratch --------
__device__ float g_P[H_*H_];        // W1^T W1
__device__ float g_Q[H_*H_];        // W2 W2^T
__device__ float g_W1T[H_*N_];      // W1T[h*N+i] = W1[i*H+h]
__device__ float g_W2T[N_*H_];      // W2T[k*H+h] = W2[h*N+k]
__device__ float g_s[B_*H_];
__device__ float g_c[B_*H_];
__device__ float g_Avec[B_*N_];
__device__ float g_Cvec[B_*N_];
__device__ float g_vn[B_];
__device__ float g_A2[B_*H_*H_];    // A2 = P S Q per sample
__device__ float g_part[B_*16];     // nrm^2/2 tile partials
__device__ unsigned int g_cnt[B_];  // last-block-done counters
__device__ unsigned int g_trdone;   // transpose-done counter (reset by k_A2)

#define FFMA2(d, a, b) \
    asm("fma.rn.f32x2 %0, %1, %2, %0;" : "+l"(d) : "l"(a), "l"(b))
#define DUP2(d, f) \
    asm("mov.b64 %0, {%1, %1};" : "=l"(d) : "f"(f))
#define UNPK2(lo, hi, d) \
    asm("mov.b64 {%0, %1}, %2;" : "=f"(lo), "=f"(hi) : "l"(d))

#define MICRO_STEP_F32X2(As_, Bs_)                                      \
    {   float4 ra = *(const float4*)&As_[k][ty*4];                      \
        ulonglong2 rbp = *(const ulonglong2*)&Bs_[k][tx*4];             \
        unsigned long long ad0, ad1, ad2, ad3;                          \
        DUP2(ad0, ra.x); DUP2(ad1, ra.y);                               \
        DUP2(ad2, ra.z); DUP2(ad3, ra.w);                               \
        FFMA2(accp[0][0], ad0, rbp.x); FFMA2(accp[0][1], ad0, rbp.y);   \
        FFMA2(accp[1][0], ad1, rbp.x); FFMA2(accp[1][1], ad1, rbp.y);   \
        FFMA2(accp[2][0], ad2, rbp.x); FFMA2(accp[2][1], ad2, rbp.y);   \
        FFMA2(accp[3][0], ad3, rbp.x); FFMA2(accp[3][1], ad3, rbp.y);   \
    }

#define UNPACK_ACC()                                                    \
    float acc[4][4];                                                    \
    _Pragma("unroll")                                                   \
    for (int i = 0; i < 4; i++){                                        \
        UNPK2(acc[i][0], acc[i][1], accp[i][0]);                        \
        UNPK2(acc[i][2], acc[i][3], accp[i][1]);                        \
    }

// ==================== stage 1: transposes + P/Q GEMM + vectors ====================
// bid 0..63: transposes; 64..95: P/Q tiles; 96..111: per-sample vectors.
__global__ void __launch_bounds__(256) k_stage1(
        const float* __restrict__ W1, const float* __restrict__ W2,
        const float* __restrict__ tptr, const float* __restrict__ state,
        const float* __restrict__ x0,  const float* __restrict__ x1,
        const float* __restrict__ b1){
    int bid = blockIdx.x;
    int tid = threadIdx.x;

    if (bid < 64){
        // ---- transposes: W1 -> W1T (bid<32), W2 -> W2T (bid>=32) ----
        __shared__ float ts[32][33];
        int r0 = tid >> 5, cc = tid & 31;
        if (bid < 32){
            int ti = bid >> 3, th = bid & 7;
            #pragma unroll
            for (int r = r0; r < 32; r += 8)
                ts[r][cc] = W1[(ti*32 + r)*H_ + th*32 + cc];
            __syncthreads();
            #pragma unroll
            for (int r = r0; r < 32; r += 8)
                g_W1T[(th*32 + r)*N_ + ti*32 + cc] = ts[cc][r];
        } else {
            int b2 = bid - 32;
            int th = b2 >> 2, tk = b2 & 3;
            #pragma unroll
            for (int r = r0; r < 32; r += 8)
                ts[r][cc] = W2[(th*32 + r)*N_ + tk*32 + cc];
            __syncthreads();
            #pragma unroll
            for (int r = r0; r < 32; r += 8)
                g_W2T[(tk*32 + r)*H_ + th*32 + cc] = ts[cc][r];
        }
        __threadfence();
        __syncthreads();
        if (tid == 0) atomicAdd(&g_trdone, 1u);
        return;
    }

    if (bid < 96){
        // ---- P = W1^T W1 (z=0) or Q = W2 W2^T (z=1), 64x64 tile ----
        int z = (bid - 64) >> 4, tile = (bid - 64) & 15;
        int g0 = (tile >> 2)*64, h0 = (tile & 3)*64;
        __shared__ float As[16][68];
        __shared__ float Bs[16][68];
        int ty = tid >> 4, tx = tid & 15;
        unsigned long long accp[4][2] = {{0ull,0ull},{0ull,0ull},{0ull,0ull},{0ull,0ull}};

        for (int a0 = 0; a0 < N_; a0 += 16){
            if (z == 0){
                int a = tid >> 4, q4 = (tid & 15)*4;
                *(float4*)&As[a][q4] = *(const float4*)&W1[(a0+a)*H_ + g0 + q4];
                *(float4*)&Bs[a][q4] = *(const float4*)&W1[(a0+a)*H_ + h0 + q4];
            } else {
                int gg = tid >> 2, kq = (tid & 3)*4;
                float4 av = *(const float4*)&W2[(g0+gg)*N_ + a0 + kq];
                float4 bv = *(const float4*)&W2[(h0+gg)*N_ + a0 + kq];
                As[kq+0][gg] = av.x; As[kq+1][gg] = av.y;
                As[kq+2][gg] = av.z; As[kq+3][gg] = av.w;
                Bs[kq+0][gg] = bv.x; Bs[kq+1][gg] = bv.y;
                Bs[kq+2][gg] = bv.z; Bs[kq+3][gg] = bv.w;
            }
            __syncthreads();
            #pragma unroll
            for (int k = 0; k < 16; k++) MICRO_STEP_F32X2(As, Bs)
            __syncthreads();
        }
        UNPACK_ACC()
        float* dst = (z == 0) ? g_P : g_Q;
        #pragma unroll
        for (int i = 0; i < 4; i++){
            float4 o = make_float4(acc[i][0], acc[i][1], acc[i][2], acc[i][3]);
            *(float4*)&dst[(g0+ty*4+i)*H_ + h0 + tx*4] = o;
        }
        return;
    }

    // ---- per-sample vector pipeline ----
    int b = bid - 96;
    __shared__ float xs[N_], vs[N_], red[N_];
    __shared__ float swv[H_], cwy[H_], pvs[H_], cwz[H_];
    __shared__ float r1p[2][N_], r2p[2][N_], r1s[N_], r2s[N_];
    __shared__ float Ap[2][N_], Cp[2][N_];

    float tval = *tptr;
    float window = 4.f * tval * (1.f - tval);
    if (tid < N_){
        float dev = state[b*N_ + tid];
        float v   = state[(B_+b)*N_ + tid];
        float x0v = x0[b*N_ + tid];
        xs[tid] = x0v + tval*(x1[b*N_ + tid] - x0v) + window*dev;
        vs[tid] = v;
        red[tid] = v*v;
    }
    __syncthreads();

    if (tid < 32){
        float a0 = red[tid] + red[tid+32] + red[tid+64] + red[tid+96];
        #pragma unroll
        for (int o = 16; o; o >>= 1) a0 += __shfl_xor_sync(0xffffffffu, a0, o);
        if (tid == 0) g_vn[b] = sqrtf(a0);
    }

    int h = tid;
    // u, y from W1 (no transpose needed) -- overlaps with transpose blocks
    float u = 0.f, y = 0.f;
    #pragma unroll 8
    for (int k = 0; k < N_; k++){
        float w1 = W1[k*H_ + h];
        u += xs[k]*w1;
        y += vs[k]*w1;
    }

    // wait for W1T/W2T
    if (tid == 0){
        volatile unsigned int* p = &g_trdone;
        while (*p != 64u) {}
        __threadfence();
    }
    __syncthreads();

    // w from W2T -- coalesced
    float w = 0.f;
    #pragma unroll 8
    for (int k = 0; k < N_; k++)
        w += g_W2T[k*H_ + h]*vs[k];

    float th = tanhf(u + b1[h]);
    float s = 1.f - th*th;
    float c = -2.f*th*s;
    g_s[b*H_ + h] = s;
    g_c[b*H_ + h] = c;
    swv[h] = s*w;
    cwy[h] = c*w*y;
    __syncthreads();

    // r1 = W1*swv, r2 = W1*cwy via W1T (2 threads per output)
    {
        int kk = tid & 127, half = tid >> 7;
        float s1 = 0.f, s2 = 0.f;
        #pragma unroll 8
        for (int j = 0; j < 128; j++){
            int hh = half*128 + j;
            float w1t = g_W1T[hh*N_ + kk];
            s1 += w1t*swv[hh];
            s2 += w1t*cwy[hh];
        }
        r1p[half][kk] = s1;
        r2p[half][kk] = s2;
    }
    __syncthreads();
    if (tid < N_){
        r1s[tid] = r1p[0][tid] + r1p[1][tid];
        r2s[tid] = r2p[0][tid] + r2p[1][tid];
    }
    __syncthreads();

    // z = W1^T r1, q2 = W1^T r2 -- coalesced
    float z = 0.f, q2 = 0.f;
    #pragma unroll 8
    for (int k = 0; k < N_; k++){
        float w1 = W1[k*H_ + h];
        z  += w1*r1s[k];
        q2 += w1*r2s[k];
    }
    pvs[h] = c*y*z + s*q2;
    cwz[h] = c*w*z;
    __syncthreads();

    // A = W2^T pv (via W2), C = W1 cwz (via W1T)
    {
        int i = tid & 127, hf = tid >> 7;
        float A = 0.f, Cc = 0.f;
        #pragma unroll 8
        for (int j = 0; j < 128; j++){
            int hh = hf*128 + j;
            A  += W2[hh*N_ + i]*pvs[hh];
            Cc += g_W1T[hh*N_ + i]*cwz[hh];
        }
        Ap[hf][i] = A;
        Cp[hf][i] = Cc;
    }
    __syncthreads();
    if (tid < N_){
        g_Avec[b*N_ + tid] = Ap[0][tid] + Ap[1][tid];
        g_Cvec[b*N_ + tid] = 2.f*(Cp[0][tid] + Cp[1][tid]);
    }
}

// ==================== stage 2: A2[b] = P diag(s) Q (double-buffered) ====================
__global__ void __launch_bounds__(256) k_A2(){
    int b  = blockIdx.z;
    int g0 = blockIdx.y*64, h0 = blockIdx.x*64;
    int tid = threadIdx.x;
    if (blockIdx.x == 0 && blockIdx.y == 0 && tid == 0){
        g_cnt[b] = 0;                    // for k_nrm's last-block pattern
        if (b == 0) g_trdone = 0;        // reset for next replay
    }
    int ty = tid >> 4, tx = tid & 15;
    __shared__ float Ps[2][16][68];
    __shared__ float Qs[2][16][68];
    __shared__ float ssm[H_];
    ssm[tid] = g_s[b*H_ + tid];
    unsigned long long accp[4][2] = {{0ull,0ull},{0ull,0ull},{0ull,0ull},{0ull,0ull}};

    int a = tid >> 4, q4 = (tid & 15)*4;
    float4 pv = *(const float4*)&g_P[a*H_ + g0 + q4];     // tile 0 (P symmetric)
    float4 qv = *(const float4*)&g_Q[a*H_ + h0 + q4];
    __syncthreads();                                      // ssm ready
    {
        float sa = ssm[a];
        *(float4*)&Ps[0][a][q4] = pv;
        qv.x *= sa; qv.y *= sa; qv.z *= sa; qv.w *= sa;
        *(float4*)&Qs[0][a][q4] = qv;
    }
    __syncthreads();

    for (int t = 0; t < 16; t++){
        int cur = t & 1;
        if (t < 15){
            pv = *(const float4*)&g_P[((t+1)*16 + a)*H_ + g0 + q4];
            qv = *(const float4*)&g_Q[((t+1)*16 + a)*H_ + h0 + q4];
        }
        #pragma unroll
        for (int k = 0; k < 16; k++) MICRO_STEP_F32X2(Ps[cur], Qs[cur])
        if (t < 15){
            float sa = ssm[(t+1)*16 + a];
            *(float4*)&Ps[cur^1][a][q4] = pv;
            qv.x *= sa; qv.y *= sa; qv.z *= sa; qv.w *= sa;
            *(float4*)&Qs[cur^1][a][q4] = qv;
        }
        __syncthreads();
    }
    UNPACK_ACC()
    float* dst = g_A2 + b*H_*H_;
    #pragma unroll
    for (int i = 0; i < 4; i++){
        float4 o = make_float4(acc[i][0], acc[i][1], acc[i][2], acc[i][3]);
        *(float4*)&dst[(g0+ty*4+i)*H_ + h0 + tx*4] = o;
    }
}

// ========== stage 3: M = P diag(s) A2^T, fused reduction + finalize ==========
// Term1 = sum w.Q.M (w, Q symmetric => equals sum w.Q.A1); Term2 via mirror tile.
__global__ void __launch_bounds__(256) k_nrm(const float* __restrict__ state,
                                             float* __restrict__ out){
    int b  = blockIdx.z;
    int g0 = blockIdx.y*64, h0 = blockIdx.x*64;
    int tid = threadIdx.x;
    int ty = tid >> 4, tx = tid & 15;
    __shared__ float As[2][16][68];
    __shared__ float Bs[2][16][68];
    __shared__ float Ts[64][65];       // mirror tile A2[h0.., g0..]
    __shared__ float ssm[H_];
    ssm[tid] = g_s[b*H_ + tid];
    unsigned long long accp[4][2] = {{0ull,0ull},{0ull,0ull},{0ull,0ull},{0ull,0ull}};

    const float* A2b = g_A2 + b*H_*H_;
    int a  = tid >> 4, q4 = (tid & 15)*4;   // As mapping (P rows)
    int rw = tid >> 2, kq = (tid & 3)*4;    // Bs mapping (A2 rows, k-minor)

    // mirror tile: coalesced load, transposed read later
    #pragma unroll
    for (int p = 0; p < 4; p++){
        int f = tid + p*256;
        int row = f >> 4, c4 = (f & 15)*4;
        float4 tv = *(const float4*)&A2b[(h0+row)*H_ + g0 + c4];
        Ts[row][c4+0] = tv.x; Ts[row][c4+1] = tv.y;
        Ts[row][c4+2] = tv.z; Ts[row][c4+3] = tv.w;
    }

    float4 pv = *(const float4*)&g_P[a*H_ + g0 + q4];         // tile 0
    float4 bv = *(const float4*)&A2b[(h0+rw)*H_ + kq];
    __syncthreads();                                          // ssm ready
    {
        float sa = ssm[a];
        pv.x *= sa; pv.y *= sa; pv.z *= sa; pv.w *= sa;
        *(float4*)&As[0][a][q4] = pv;
        Bs[0][kq+0][rw] = bv.x; Bs[0][kq+1][rw] = bv.y;
        Bs[0][kq+2][rw] = bv.z; Bs[0][kq+3][rw] = bv.w;
    }
    __syncthreads();

    for (int t = 0; t < 16; t++){
        int cur = t & 1;
        if (t < 15){
            pv = *(const float4*)&g_P[((t+1)*16 + a)*H_ + g0 + q4];
            bv = *(const float4*)&A2b[(h0+rw)*H_ + (t+1)*16 + kq];
        }
        #pragma unroll
        for (int k = 0; k < 16; k++) MICRO_STEP_F32X2(As[cur], Bs[cur])
        if (t < 15){
            float sa = ssm[(t+1)*16 + a];
            pv.x *= sa; pv.y *= sa; pv.z *= sa; pv.w *= sa;
            *(float4*)&As[cur^1][a][q4] = pv;
            Bs[cur^1][kq+0][rw] = bv.x; Bs[cur^1][kq+1][rw] = bv.y;
            Bs[cur^1][kq+2][rw] = bv.z; Bs[cur^1][kq+3][rw] = bv.w;
        }
        __syncthreads();
    }
    UNPACK_ACC()   // acc[i][j] = M[g0+ty*4+i][h0+tx*4+j] = A1[h][g]

    const float* cb = g_c + b*H_;
    float local = 0.f;
    #pragma unroll
    for (int i = 0; i < 4; i++){
        int g = g0 + ty*4 + i;
        float cg = cb[g];
        float4 P4  = *(const float4*)&g_P[g*H_ + h0 + tx*4];
        float4 Q4  = *(const float4*)&g_Q[g*H_ + h0 + tx*4];
        float4 A4  = *(const float4*)&A2b[g*H_ + h0 + tx*4];
        float pr[4] = {P4.x, P4.y, P4.z, P4.w};
        float qr[4] = {Q4.x, Q4.y, Q4.z, Q4.w};
        float ar[4] = {A4.x, A4.y, A4.z, A4.w};
        #pragma unroll
        for (int j = 0; j < 4; j++){
            int h = h0 + tx*4 + j;
            float a2t = Ts[tx*4+j][ty*4+i];       // A2[h][g]
            local += cg*cb[h]*pr[j]*(qr[j]*acc[i][j] + ar[j]*a2t);
        }
    }
    __shared__ float red[256];
    red[tid] = local;
    __syncthreads();
    for (int st = 128; st > 0; st >>= 1){
        if (tid < st) red[tid] += red[tid + st];
        __syncthreads();
    }
    __shared__ unsigned int is_last;
    if (tid == 0){
        g_part[b*16 + blockIdx.y*4 + blockIdx.x] = red[0];
        __threadfence();
        is_last = (atomicAdd(&g_cnt[b], 1u) == 15u);
    }
    __syncthreads();

    if (is_last && tid < N_){
        float sum = 0.f;
        #pragma unroll
        for (int i = 0; i < 16; i++) sum += g_part[b*16 + i];
        float nrm = sqrtf(fmaxf(2.f*sum, 0.f));
        float vn  = g_vn[b];
        float v   = state[(B_+b)*N_ + tid];
        float dev = state[b*N_ + tid];
        float aout = -(g_Avec[b*N_ + tid] - 0.5f*g_Cvec[b*N_ + tid])
                     / ((nrm + 1e-6f) * (vn + 1e-6f));
        out[b*N_ + tid]       = v;
        out[(B_+b)*N_ + tid]  = aout - 0.1f*dev;
    }
}

// -------- launch --------
extern "C" void kernel_launch(void* const* d_in, const int* in_sizes, int n_in,
                              void* d_out, int out_size){
    const float* t     = (const float*)d_in[0];
    const float* state = (const float*)d_in[1];
    const float* x0    = (const float*)d_in[2];
    const float* x1    = (const float*)d_in[3];
    const float* W1    = (const float*)d_in[4];
    const float* b1    = (const float*)d_in[5];
    const float* W2    = (const float*)d_in[6];
    float* out = (float*)d_out;

    k_stage1<<<112,          256>>>(W1, W2, t, state, x0, x1, b1);
    k_A2    <<<dim3(4,4,B_), 256>>>();
    k_nrm   <<<dim3(4,4,B_), 256>>>(state, out);
}

// round 11
// speedup vs baseline: 1.1694x; 1.1694x over previous
#include <cuda_runtime.h>
#include <math.h>

#define N_ 128
#define H_ 256
#define B_ 16

// -------- device scratch --------
__device__ float g_P[H_*H_];        // W1^T W1
__device__ float g_Q[H_*H_];        // W2 W2^T
__device__ float g_W1T[H_*N_];      // W1T[h*N+i] = W1[i*H+h]
__device__ float g_W2T[N_*H_];      // W2T[k*H+h] = W2[h*N+k]
__device__ float g_s[B_*H_];
__device__ float g_c[B_*H_];
__device__ float g_Avec[B_*N_];
__device__ float g_Cvec[B_*N_];
__device__ float g_vn[B_];
__device__ float g_A2[B_*H_*H_];    // A2 = P S Q per sample
__device__ float g_part[B_*16];     // nrm^2/2 tile partials
__device__ unsigned int g_cnt[B_];  // last-block-done counters

#define FFMA2(d, a, b) \
    asm("fma.rn.f32x2 %0, %1, %2, %0;" : "+l"(d) : "l"(a), "l"(b))
#define DUP2(d, f) \
    asm("mov.b64 %0, {%1, %1};" : "=l"(d) : "f"(f))
#define UNPK2(lo, hi, d) \
    asm("mov.b64 {%0, %1}, %2;" : "=f"(lo), "=f"(hi) : "l"(d))

#define MICRO_STEP_F32X2(As_, Bs_)                                      \
    {   float4 ra = *(const float4*)&As_[k][ty*4];                      \
        ulonglong2 rbp = *(const ulonglong2*)&Bs_[k][tx*4];             \
        unsigned long long ad0, ad1, ad2, ad3;                          \
        DUP2(ad0, ra.x); DUP2(ad1, ra.y);                               \
        DUP2(ad2, ra.z); DUP2(ad3, ra.w);                               \
        FFMA2(accp[0][0], ad0, rbp.x); FFMA2(accp[0][1], ad0, rbp.y);   \
        FFMA2(accp[1][0], ad1, rbp.x); FFMA2(accp[1][1], ad1, rbp.y);   \
        FFMA2(accp[2][0], ad2, rbp.x); FFMA2(accp[2][1], ad2, rbp.y);   \
        FFMA2(accp[3][0], ad3, rbp.x); FFMA2(accp[3][1], ad3, rbp.y);   \
    }

#define UNPACK_ACC()                                                    \
    float acc[4][4];                                                    \
    _Pragma("unroll")                                                   \
    for (int i = 0; i < 4; i++){                                        \
        UNPK2(acc[i][0], acc[i][1], accp[i][0]);                        \
        UNPK2(acc[i][2], acc[i][3], accp[i][1]);                        \
    }

// ==================== kernel 0: transposes ====================
__global__ void __launch_bounds__(256) k_tr(const float* __restrict__ W1,
                                            const float* __restrict__ W2){
    __shared__ float ts[32][33];
    int bid = blockIdx.x;
    int tid = threadIdx.x;
    int r0 = tid >> 5, cc = tid & 31;
    if (bid < 32){
        int ti = bid >> 3, th = bid & 7;
        #pragma unroll
        for (int r = r0; r < 32; r += 8)
            ts[r][cc] = W1[(ti*32 + r)*H_ + th*32 + cc];
        __syncthreads();
        #pragma unroll
        for (int r = r0; r < 32; r += 8)
            g_W1T[(th*32 + r)*N_ + ti*32 + cc] = ts[cc][r];
    } else {
        int b2 = bid - 32;
        int th = b2 >> 2, tk = b2 & 3;
        #pragma unroll
        for (int r = r0; r < 32; r += 8)
            ts[r][cc] = W2[(th*32 + r)*N_ + tk*32 + cc];
        __syncthreads();
        #pragma unroll
        for (int r = r0; r < 32; r += 8)
            g_W2T[(tk*32 + r)*H_ + th*32 + cc] = ts[cc][r];
    }
}

// ==================== stage 1: fused P/Q GEMM + vectors ====================
// blocks 0..15: P tiles, 16..31: Q tiles, 32..47: per-sample vectors.
__global__ void __launch_bounds__(256) k_stage1(
        const float* __restrict__ W1, const float* __restrict__ W2,
        const float* __restrict__ tptr, const float* __restrict__ state,
        const float* __restrict__ x0,  const float* __restrict__ x1,
        const float* __restrict__ b1){
    int bid = blockIdx.x;
    int tid = threadIdx.x;

    if (bid < 32){
        int z = bid >> 4, tile = bid & 15;
        int g0 = (tile >> 2)*64, h0 = (tile & 3)*64;
        __shared__ float As[16][68];
        __shared__ float Bs[16][68];
        int ty = tid >> 4, tx = tid & 15;
        unsigned long long accp[4][2] = {{0ull,0ull},{0ull,0ull},{0ull,0ull},{0ull,0ull}};

        for (int a0 = 0; a0 < N_; a0 += 16){
            if (z == 0){
                int a = tid >> 4, q4 = (tid & 15)*4;
                *(float4*)&As[a][q4] = *(const float4*)&W1[(a0+a)*H_ + g0 + q4];
                *(float4*)&Bs[a][q4] = *(const float4*)&W1[(a0+a)*H_ + h0 + q4];
            } else {
                int gg = tid >> 2, kq = (tid & 3)*4;
                float4 av = *(const float4*)&W2[(g0+gg)*N_ + a0 + kq];
                float4 bv = *(const float4*)&W2[(h0+gg)*N_ + a0 + kq];
                As[kq+0][gg] = av.x; As[kq+1][gg] = av.y;
                As[kq+2][gg] = av.z; As[kq+3][gg] = av.w;
                Bs[kq+0][gg] = bv.x; Bs[kq+1][gg] = bv.y;
                Bs[kq+2][gg] = bv.z; Bs[kq+3][gg] = bv.w;
            }
            __syncthreads();
            #pragma unroll
            for (int k = 0; k < 16; k++) MICRO_STEP_F32X2(As, Bs)
            __syncthreads();
        }
        UNPACK_ACC()
        float* dst = (z == 0) ? g_P : g_Q;
        #pragma unroll
        for (int i = 0; i < 4; i++){
            float4 o = make_float4(acc[i][0], acc[i][1], acc[i][2], acc[i][3]);
            *(float4*)&dst[(g0+ty*4+i)*H_ + h0 + tx*4] = o;
        }
        return;
    }

    // ---- per-sample vector pipeline: forced-MLP register batches ----
    int b = bid - 32;
    __shared__ float xs[N_], vs[N_], red[N_];
    __shared__ float swv[H_], cwy[H_], pvs[H_], cwz[H_];
    __shared__ float r1p[2][N_], r2p[2][N_], r1s[N_], r2s[N_];
    __shared__ float Ap[2][N_], Cp[2][N_];

    float tval = *tptr;
    float window = 4.f * tval * (1.f - tval);
    if (tid < N_){
        float dev = state[b*N_ + tid];
        float v   = state[(B_+b)*N_ + tid];
        float x0v = x0[b*N_ + tid];
        xs[tid] = x0v + tval*(x1[b*N_ + tid] - x0v) + window*dev;
        vs[tid] = v;
        red[tid] = v*v;
    }
    __syncthreads();

    if (tid < 32){
        float a0 = red[tid] + red[tid+32] + red[tid+64] + red[tid+96];
        #pragma unroll
        for (int o = 16; o; o >>= 1) a0 += __shfl_xor_sync(0xffffffffu, a0, o);
        if (tid == 0) g_vn[b] = sqrtf(a0);
    }

    int h = tid;
    // phase B: u, y, w with explicit 16-deep load batches (MLP ~32)
    float u = 0.f, y = 0.f, w = 0.f;
    for (int k0 = 0; k0 < N_; k0 += 16){
        float wb[16], tb[16];
        #pragma unroll
        for (int j = 0; j < 16; j++) wb[j] = W1[(k0+j)*H_ + h];
        #pragma unroll
        for (int j = 0; j < 16; j++) tb[j] = g_W2T[(k0+j)*H_ + h];
        #pragma unroll
        for (int j = 0; j < 16; j++){
            u += xs[k0+j]*wb[j];
            y += vs[k0+j]*wb[j];
            w += vs[k0+j]*tb[j];
        }
    }
    float th = tanhf(u + b1[h]);
    float s = 1.f - th*th;
    float c = -2.f*th*s;
    g_s[b*H_ + h] = s;
    g_c[b*H_ + h] = c;
    swv[h] = s*w;
    cwy[h] = c*w*y;
    __syncthreads();

    // phase C: r1 = W1*swv, r2 = W1*cwy via W1T (2 threads per output k)
    {
        int kk = tid & 127, half = tid >> 7;
        float s1 = 0.f, s2 = 0.f;
        for (int j0 = 0; j0 < 128; j0 += 16){
            float wb[16];
            #pragma unroll
            for (int j = 0; j < 16; j++) wb[j] = g_W1T[(half*128 + j0 + j)*N_ + kk];
            #pragma unroll
            for (int j = 0; j < 16; j++){
                s1 += wb[j]*swv[half*128 + j0 + j];
                s2 += wb[j]*cwy[half*128 + j0 + j];
            }
        }
        r1p[half][kk] = s1;
        r2p[half][kk] = s2;
    }
    __syncthreads();
    if (tid < N_){
        r1s[tid] = r1p[0][tid] + r1p[1][tid];
        r2s[tid] = r2p[0][tid] + r2p[1][tid];
    }
    __syncthreads();

    // phase D: z = W1^T r1, q2 = W1^T r2
    float z = 0.f, q2 = 0.f;
    for (int k0 = 0; k0 < N_; k0 += 16){
        float wb[16];
        #pragma unroll
        for (int j = 0; j < 16; j++) wb[j] = W1[(k0+j)*H_ + h];
        #pragma unroll
        for (int j = 0; j < 16; j++){
            z  += wb[j]*r1s[k0+j];
            q2 += wb[j]*r2s[k0+j];
        }
    }
    pvs[h] = c*y*z + s*q2;
    cwz[h] = c*w*z;
    __syncthreads();

    // phase E: A = W2^T pv (via W2), C = W1 cwz (via W1T)
    {
        int i = tid & 127, hf = tid >> 7;
        float A = 0.f, Cc = 0.f;
        for (int j0 = 0; j0 < 128; j0 += 16){
            float wa[16], wc[16];
            #pragma unroll
            for (int j = 0; j < 16; j++) wa[j] = W2[(hf*128 + j0 + j)*N_ + i];
            #pragma unroll
            for (int j = 0; j < 16; j++) wc[j] = g_W1T[(hf*128 + j0 + j)*N_ + i];
            #pragma unroll
            for (int j = 0; j < 16; j++){
                A  += wa[j]*pvs[hf*128 + j0 + j];
                Cc += wc[j]*cwz[hf*128 + j0 + j];
            }
        }
        Ap[hf][i] = A;
        Cp[hf][i] = Cc;
    }
    __syncthreads();
    if (tid < N_){
        g_Avec[b*N_ + tid] = Ap[0][tid] + Ap[1][tid];
        g_Cvec[b*N_ + tid] = 2.f*(Cp[0][tid] + Cp[1][tid]);
    }
}

// ==================== stage 2: A2[b] = P diag(s) Q (double-buffered) ====================
__global__ void __launch_bounds__(256) k_A2(){
    int b  = blockIdx.z;
    int g0 = blockIdx.y*64, h0 = blockIdx.x*64;
    int tid = threadIdx.x;
    if (blockIdx.x == 0 && blockIdx.y == 0 && tid == 0) g_cnt[b] = 0;
    int ty = tid >> 4, tx = tid & 15;
    __shared__ float Ps[2][16][68];
    __shared__ float Qs[2][16][68];
    __shared__ float ssm[H_];
    ssm[tid] = g_s[b*H_ + tid];
    unsigned long long accp[4][2] = {{0ull,0ull},{0ull,0ull},{0ull,0ull},{0ull,0ull}};

    int a = tid >> 4, q4 = (tid & 15)*4;
    float4 pv = *(const float4*)&g_P[a*H_ + g0 + q4];     // tile 0 (P symmetric)
    float4 qv = *(const float4*)&g_Q[a*H_ + h0 + q4];
    __syncthreads();                                      // ssm ready
    {
        float sa = ssm[a];
        *(float4*)&Ps[0][a][q4] = pv;
        qv.x *= sa; qv.y *= sa; qv.z *= sa; qv.w *= sa;
        *(float4*)&Qs[0][a][q4] = qv;
    }
    __syncthreads();

    for (int t = 0; t < 16; t++){
        int cur = t & 1;
        if (t < 15){
            pv = *(const float4*)&g_P[((t+1)*16 + a)*H_ + g0 + q4];
            qv = *(const float4*)&g_Q[((t+1)*16 + a)*H_ + h0 + q4];
        }
        #pragma unroll
        for (int k = 0; k < 16; k++) MICRO_STEP_F32X2(Ps[cur], Qs[cur])
        if (t < 15){
            float sa = ssm[(t+1)*16 + a];
            *(float4*)&Ps[cur^1][a][q4] = pv;
            qv.x *= sa; qv.y *= sa; qv.z *= sa; qv.w *= sa;
            *(float4*)&Qs[cur^1][a][q4] = qv;
        }
        __syncthreads();
    }
    UNPACK_ACC()
    float* dst = g_A2 + b*H_*H_;
    #pragma unroll
    for (int i = 0; i < 4; i++){
        float4 o = make_float4(acc[i][0], acc[i][1], acc[i][2], acc[i][3]);
        *(float4*)&dst[(g0+ty*4+i)*H_ + h0 + tx*4] = o;
    }
}

// ========== stage 3: M = P diag(s) A2^T, fused reduction + finalize ==========
__global__ void __launch_bounds__(256) k_nrm(const float* __restrict__ state,
                                             float* __restrict__ out){
    int b  = blockIdx.z;
    int g0 = blockIdx.y*64, h0 = blockIdx.x*64;
    int tid = threadIdx.x;
    int ty = tid >> 4, tx = tid & 15;
    __shared__ float As[2][16][68];
    __shared__ float Bs[2][16][68];
    __shared__ float Ts[64][65];       // mirror tile A2[h0.., g0..]
    __shared__ float ssm[H_];
    ssm[tid] = g_s[b*H_ + tid];
    unsigned long long accp[4][2] = {{0ull,0ull},{0ull,0ull},{0ull,0ull},{0ull,0ull}};

    const float* A2b = g_A2 + b*H_*H_;
    int a  = tid >> 4, q4 = (tid & 15)*4;
    int rw = tid >> 2, kq = (tid & 3)*4;

    #pragma unroll
    for (int p = 0; p < 4; p++){
        int f = tid + p*256;
        int row = f >> 4, c4 = (f & 15)*4;
        float4 tv = *(const float4*)&A2b[(h0+row)*H_ + g0 + c4];
        Ts[row][c4+0] = tv.x; Ts[row][c4+1] = tv.y;
        Ts[row][c4+2] = tv.z; Ts[row][c4+3] = tv.w;
    }

    float4 pv = *(const float4*)&g_P[a*H_ + g0 + q4];
    float4 bv = *(const float4*)&A2b[(h0+rw)*H_ + kq];
    __syncthreads();
    {
        float sa = ssm[a];
        pv.x *= sa; pv.y *= sa; pv.z *= sa; pv.w *= sa;
        *(float4*)&As[0][a][q4] = pv;
        Bs[0][kq+0][rw] = bv.x; Bs[0][kq+1][rw] = bv.y;
        Bs[0][kq+2][rw] = bv.z; Bs[0][kq+3][rw] = bv.w;
    }
    __syncthreads();

    for (int t = 0; t < 16; t++){
        int cur = t & 1;
        if (t < 15){
            pv = *(const float4*)&g_P[((t+1)*16 + a)*H_ + g0 + q4];
            bv = *(const float4*)&A2b[(h0+rw)*H_ + (t+1)*16 + kq];
        }
        #pragma unroll
        for (int k = 0; k < 16; k++) MICRO_STEP_F32X2(As[cur], Bs[cur])
        if (t < 15){
            float sa = ssm[(t+1)*16 + a];
            pv.x *= sa; pv.y *= sa; pv.z *= sa; pv.w *= sa;
            *(float4*)&As[cur^1][a][q4] = pv;
            Bs[cur^1][kq+0][rw] = bv.x; Bs[cur^1][kq+1][rw] = bv.y;
            Bs[cur^1][kq+2][rw] = bv.z; Bs[cur^1][kq+3][rw] = bv.w;
        }
        __syncthreads();
    }
    UNPACK_ACC()   // acc[i][j] = M[g][h] = A1[h][g]

    const float* cb = g_c + b*H_;
    float local = 0.f;
    #pragma unroll
    for (int i = 0; i < 4; i++){
        int g = g0 + ty*4 + i;
        float cg = cb[g];
        float4 P4  = *(const float4*)&g_P[g*H_ + h0 + tx*4];
        float4 Q4  = *(const float4*)&g_Q[g*H_ + h0 + tx*4];
        float4 A4  = *(const float4*)&A2b[g*H_ + h0 + tx*4];
        float pr[4] = {P4.x, P4.y, P4.z, P4.w};
        float qr[4] = {Q4.x, Q4.y, Q4.z, Q4.w};
        float ar[4] = {A4.x, A4.y, A4.z, A4.w};
        #pragma unroll
        for (int j = 0; j < 4; j++){
            int hcol = h0 + tx*4 + j;
            float a2t = Ts[tx*4+j][ty*4+i];
            local += cg*cb[hcol]*pr[j]*(qr[j]*acc[i][j] + ar[j]*a2t);
        }
    }
    __shared__ float red[256];
    red[tid] = local;
    __syncthreads();
    for (int st = 128; st > 0; st >>= 1){
        if (tid < st) red[tid] += red[tid + st];
        __syncthreads();
    }
    __shared__ unsigned int is_last;
    if (tid == 0){
        g_part[b*16 + blockIdx.y*4 + blockIdx.x] = red[0];
        __threadfence();
        is_last = (atomicAdd(&g_cnt[b], 1u) == 15u);
    }
    __syncthreads();

    if (is_last && tid < N_){
        float sum = 0.f;
        #pragma unroll
        for (int i = 0; i < 16; i++) sum += g_part[b*16 + i];
        float nrm = sqrtf(fmaxf(2.f*sum, 0.f));
        float vn  = g_vn[b];
        float v   = state[(B_+b)*N_ + tid];
        float dev = state[b*N_ + tid];
        float aout = -(g_Avec[b*N_ + tid] - 0.5f*g_Cvec[b*N_ + tid])
                     / ((nrm + 1e-6f) * (vn + 1e-6f));
        out[b*N_ + tid]       = v;
        out[(B_+b)*N_ + tid]  = aout - 0.1f*dev;
    }
}

// -------- launch --------
extern "C" void kernel_launch(void* const* d_in, const int* in_sizes, int n_in,
                              void* d_out, int out_size){
    const float* t     = (const float*)d_in[0];
    const float* state = (const float*)d_in[1];
    const float* x0    = (const float*)d_in[2];
    const float* x1    = (const float*)d_in[3];
    const float* W1    = (const float*)d_in[4];
    const float* b1    = (const float*)d_in[5];
    const float* W2    = (const float*)d_in[6];
    float* out = (float*)d_out;

    k_tr    <<<64,           256>>>(W1, W2);
    k_stage1<<<48,           256>>>(W1, W2, t, state, x0, x1, b1);
    k_A2    <<<dim3(4,4,B_), 256>>>();
    k_nrm   <<<dim3(4,4,B_), 256>>>(state, out);
}